// round 12
// baseline (speedup 1.0000x reference)
#include <cuda_runtime.h>

#define HH 128
#define WW 128
#define CC 64
#define OO 64
#define BB 2
#define KK9 9
#define HWSZ (HH*WW)

#define RPIX 128        // pixels per main-kernel CTA (full row)
#define CH  32          // channels per main-kernel CTA (split-K half)

typedef unsigned long long ull;

// ---------------- f32x2 packed helpers -----------------------------------------
__device__ __forceinline__ ull pack2(float a, float b) {
    ull r; asm("mov.b64 %0, {%1, %2};" : "=l"(r) : "f"(a), "f"(b)); return r;
}
__device__ __forceinline__ ull bcast2(float a) {
    ull r; asm("mov.b64 %0, {%1, %1};" : "=l"(r) : "f"(a)); return r;
}
__device__ __forceinline__ void ffma2(ull& d, ull a, ull b) {
    asm("fma.rn.f32x2 %0, %1, %2, %0;" : "+l"(d) : "l"(a), "l"(b));
}
__device__ __forceinline__ void fadd2(ull& d, ull a) {
    asm("add.rn.f32x2 %0, %0, %1;" : "+l"(d) : "l"(a));
}
__device__ __forceinline__ float lo2(ull v) { return __uint_as_float((unsigned)v); }
__device__ __forceinline__ float hi2(ull v) { return __uint_as_float((unsigned)(v >> 32)); }

// ---------------- scratch (__device__ globals) ---------------------------------
__device__ int4   g_sidx[BB*HWSZ*KK9];      // clamped gather indices per (b,pix,k)
__device__ float4 g_swgt[BB*HWSZ*KK9];      // mask-folded bilinear corner weights
__device__ float  g_wt[KK9*CC*OO];          // main weight -> [k*64+c][o]
__device__ float  g_part[2][BB*OO*HWSZ];    // split-K partial outputs

// ---------------- K1: weight reorder + offset conv + bilinear precompute -------
// CTA = (b, h) row. 512 threads = (pixel w 0..127) x (channel quarter 0..3).
// Each thread: 27 conv outputs (14 f32x2) over its 16 channels; quarters
// tree-combined via smem, then cq==0 runs the bilinear epilogue.
// smem: wsh 576*28 floats (64.5 KB) | part 2*128*15 ull (30.7 KB) = 95.2 KB.
__global__ __launch_bounds__(512, 2) void offset_kernel(
    const float* __restrict__ x,
    const float* __restrict__ wsrc,   // [64][64][3][3]  main conv weight
    const float* __restrict__ offw,   // [27][64][3][3]
    const float* __restrict__ offb)   // [27]
{
    extern __shared__ float wsh[];    // 576*28 floats
    ull* part = (ull*)(wsh + 576*28); // [2][128][15]

    int b = blockIdx.x >> 7;
    int h = blockIdx.x & 127;
    int t = threadIdx.x;
    int w  = t & 127;
    int cq = t >> 7;      // channel quarter 0..3

    // main-weight reorder: wsrc[o][c][k] -> g_wt[(k*CC+c)*OO + o]
    {
        int i = blockIdx.x * 512 + t;
        if (i < OO*CC*KK9) {
            int o = i / (CC*KK9);
            int r = i % (CC*KK9);
            int c = r / KK9;
            int k = r % KK9;
            g_wt[(k*CC + c)*OO + o] = wsrc[i];
        }
    }

    // offw[j][ct] -> wsh[ct*28 + j]
    for (int i = t; i < 27*CC*KK9; i += 512) {
        int j  = i / (CC*KK9);
        int ct = i % (CC*KK9);
        wsh[ct*28 + j] = offw[i];
    }
    __syncthreads();

    ull acc2[14];
    if (cq == 0) {
        #pragma unroll
        for (int i = 0; i < 13; i++) acc2[i] = pack2(offb[2*i], offb[2*i+1]);
        acc2[13] = pack2(offb[26], 0.f);
    } else {
        #pragma unroll
        for (int i = 0; i < 14; i++) acc2[i] = 0ull;
    }

    const float* xb = x + b*CC*HWSZ;
    int c0 = cq * 16;
    for (int ci = 0; ci < 16; ci++) {
        int c = c0 + ci;
        float xv[9];
        const float* xp = xb + c*HWSZ;
        #pragma unroll
        for (int ki = 0; ki < 3; ki++) {
            int y = h - 1 + ki;
            bool yok = ((unsigned)y < HH);
            #pragma unroll
            for (int kj = 0; kj < 3; kj++) {
                int xx = w - 1 + kj;
                bool ok = yok && ((unsigned)xx < WW);
                xv[ki*3+kj] = ok ? __ldg(xp + y*WW + xx) : 0.f;
            }
        }
        const float* wc = wsh + c*KK9*28;
        #pragma unroll
        for (int tap = 0; tap < 9; tap++) {
            ull xb2 = bcast2(xv[tap]);
            const ulonglong2* wt2 = (const ulonglong2*)(wc + tap*28);
            #pragma unroll
            for (int j2 = 0; j2 < 7; j2++) {
                ulonglong2 ww = wt2[j2];
                ffma2(acc2[j2*2    ], xb2, ww.x);
                ffma2(acc2[j2*2 + 1], xb2, ww.y);
            }
        }
    }

    // tree combine: (2,3) -> (0,1), then 1 -> 0
    if (cq >= 2) {
        ull* dst = part + (long)(cq - 2)*128*15 + w*15;
        #pragma unroll
        for (int i = 0; i < 14; i++) dst[i] = acc2[i];
    }
    __syncthreads();
    if (cq < 2) {
        ull* src = part + (long)cq*128*15 + w*15;
        #pragma unroll
        for (int i = 0; i < 14; i++) fadd2(acc2[i], src[i]);
    }
    __syncthreads();
    if (cq == 1) {
        ull* dst = part + w*15;
        #pragma unroll
        for (int i = 0; i < 14; i++) dst[i] = acc2[i];
    }
    __syncthreads();
    if (cq != 0) return;

    {
        ull* src = part + w*15;
        #pragma unroll
        for (int i = 0; i < 14; i++) fadd2(acc2[i], src[i]);
    }

    float acc[27];
    #pragma unroll
    for (int j = 0; j < 27; j++)
        acc[j] = (j & 1) ? hi2(acc2[j >> 1]) : lo2(acc2[j >> 1]);

    // derive sample indices + weights
    int pix = h*WW + w;
    long base = (long)(b*HWSZ + pix) * KK9;
    #pragma unroll
    for (int k = 0; k < 9; k++) {
        int ki = k / 3, kj = k % 3;
        float py = (float)(h - 1 + ki) + acc[k];
        float px = (float)(w - 1 + kj) + acc[9+k];
        float m  = 1.f / (1.f + __expf(-acc[18+k]));
        float y0f = floorf(py), x0f = floorf(px);
        float wy = py - y0f, wx = px - x0f;
        int y0 = (int)y0f, x0 = (int)x0f;
        int y1 = y0 + 1,  x1 = x0 + 1;
        bool v0y = ((unsigned)y0 < HH), v1y = ((unsigned)y1 < HH);
        bool v0x = ((unsigned)x0 < WW), v1x = ((unsigned)x1 < WW);
        float w00 = (v0y && v0x) ? (1.f-wy)*(1.f-wx)*m : 0.f;
        float w01 = (v0y && v1x) ? (1.f-wy)*wx*m       : 0.f;
        float w10 = (v1y && v0x) ? wy*(1.f-wx)*m       : 0.f;
        float w11 = (v1y && v1x) ? wy*wx*m             : 0.f;
        int cy0 = min(max(y0,0),HH-1), cy1 = min(max(y1,0),HH-1);
        int cx0 = min(max(x0,0),WW-1), cx1 = min(max(x1,0),WW-1);
        g_sidx[base+k] = make_int4(cy0*WW+cx0, cy0*WW+cx1, cy1*WW+cx0, cy1*WW+cx1);
        g_swgt[base+k] = make_float4(w00, w01, w10, w11);
    }
}

// ---------------- K2: sample + partial GEMM (f32x2), split-K, wide tile --------
// CTA = (b, h, channel-half): full 128-pixel row x 64 o, K = 9 taps x 32 ch.
// 256 threads. Thread tile 8o x 4p: o in {tx*4+i, 32+tx*4+i} (conflict-free
// Wsh reads covering all 16 LDS 16B-bank-groups), p = ty*4..ty*4+3.
// smem: Wsh[32][64] 8KB | Ssh[32][128] 16KB = 24 KB. Grid 512.
__global__ __launch_bounds__(256, 3) void main_kernel(
    const float* __restrict__ x)
{
    extern __shared__ float sm[];
    float* Wsh = sm;                 // 2048 floats
    float* Ssh = sm + CH*OO;         // 4096 floats

    int cta   = blockIdx.x;
    int chalf = cta & 1;
    int h     = (cta >> 1) & 127;
    int b     = cta >> 8;
    int pix0  = h*WW;
    int t = threadIdx.x;

    ull acc2[8][2];
    #pragma unroll
    for (int i = 0; i < 8; i++) { acc2[i][0] = 0ull; acc2[i][1] = 0ull; }

    int tx  = t & 7;     // GEMM: o-group
    int ty  = t >> 3;    // GEMM: p-quad 0..31
    int p   = t & 127;   // sampling: pixel
    int cph = t >> 7;    // sampling: channel phase 0..1 (16 channels each)

    const float* xb = x + (b*CC + chalf*CH)*HWSZ;
    long mbase = ((long)(b*HWSZ + pix0 + p)) * KK9;

    for (int k = 0; k < KK9; k++) {
        // per-chunk metadata: one sample point per pixel (registers)
        int4   id = __ldg(&g_sidx[mbase + k]);
        float4 wv = __ldg(&g_swgt[mbase + k]);

        __syncthreads();   // previous GEMM reads done

        // load W chunk: rows (k, chalf half), contiguous 8 KB
        {
            const float4* gw = (const float4*)(g_wt + (k*CC + chalf*CH)*OO);
            float4* wsh4 = (float4*)Wsh;
            #pragma unroll
            for (int i = 0; i < 2; i++)
                wsh4[t + i*256] = gw[t + i*256];
        }

        // sampling: 16 channels per thread at the fixed sample point
        #pragma unroll 8
        for (int j = 0; j < 16; j++) {
            int c = cph*16 + j;
            const float* xp = xb + c*HWSZ;
            float s = wv.x*__ldg(xp+id.x) + wv.y*__ldg(xp+id.y)
                    + wv.z*__ldg(xp+id.z) + wv.w*__ldg(xp+id.w);
            Ssh[c*RPIX + p] = s;
        }
        __syncthreads();

        // partial GEMM: acc[8o x 4p] += W[32 x 64] * S[32 x 128] tile
        #pragma unroll 4
        for (int c = 0; c < CH; c++) {
            float4     wlo = *(const float4*)&Wsh[c*OO + tx*4];
            float4     whi = *(const float4*)&Wsh[c*OO + 32 + tx*4];
            ulonglong2 sv  = *(const ulonglong2*)&Ssh[c*RPIX + ty*4];
            ull b0 = bcast2(wlo.x), b1 = bcast2(wlo.y);
            ull b2 = bcast2(wlo.z), b3 = bcast2(wlo.w);
            ull b4 = bcast2(whi.x), b5 = bcast2(whi.y);
            ull b6 = bcast2(whi.z), b7 = bcast2(whi.w);
            ffma2(acc2[0][0], b0, sv.x); ffma2(acc2[0][1], b0, sv.y);
            ffma2(acc2[1][0], b1, sv.x); ffma2(acc2[1][1], b1, sv.y);
            ffma2(acc2[2][0], b2, sv.x); ffma2(acc2[2][1], b2, sv.y);
            ffma2(acc2[3][0], b3, sv.x); ffma2(acc2[3][1], b3, sv.y);
            ffma2(acc2[4][0], b4, sv.x); ffma2(acc2[4][1], b4, sv.y);
            ffma2(acc2[5][0], b5, sv.x); ffma2(acc2[5][1], b5, sv.y);
            ffma2(acc2[6][0], b6, sv.x); ffma2(acc2[6][1], b6, sv.y);
            ffma2(acc2[7][0], b7, sv.x); ffma2(acc2[7][1], b7, sv.y);
        }
    }

    // write partials (no bias here; K3 adds)
    float* dst = g_part[chalf];
    #pragma unroll
    for (int half = 0; half < 2; half++) {
        #pragma unroll
        for (int i = 0; i < 4; i++) {
            int o = half*32 + tx*4 + i;
            int r = half*4 + i;
            float4 v = make_float4(lo2(acc2[r][0]), hi2(acc2[r][0]),
                                   lo2(acc2[r][1]), hi2(acc2[r][1]));
            *(float4*)&dst[(long)(b*OO + o)*HWSZ + pix0 + ty*4] = v;
        }
    }
}

// ---------------- K3: combine split-K partials + bias --------------------------
__global__ __launch_bounds__(256) void combine_kernel(
    const float* __restrict__ bias,
    float* __restrict__ out)
{
    int i = blockIdx.x * 256 + threadIdx.x;          // float4 index
    int o = (i >> 12) & 63;                          // HWSZ/4 = 4096 float4 per o
    float4 a = ((const float4*)g_part[0])[i];
    float4 c = ((const float4*)g_part[1])[i];
    float bv = __ldg(&bias[o]);
    float4 r = make_float4(a.x + c.x + bv, a.y + c.y + bv,
                           a.z + c.z + bv, a.w + c.w + bv);
    ((float4*)out)[i] = r;
}

// ---------------- launch --------------------------------------------------------
extern "C" void kernel_launch(void* const* d_in, const int* in_sizes, int n_in,
                              void* d_out, int out_size)
{
    // identify inputs by element count (robust to ordering)
    const float *x = 0, *wt = 0, *bs = 0, *ow = 0, *ob = 0;
    for (int i = 0; i < n_in; i++) {
        switch (in_sizes[i]) {
            case BB*CC*HWSZ:   x  = (const float*)d_in[i]; break; // 2097152
            case OO*CC*KK9:    wt = (const float*)d_in[i]; break; // 36864
            case OO:           bs = (const float*)d_in[i]; break; // 64
            case 27*CC*KK9:    ow = (const float*)d_in[i]; break; // 15552
            case 27:           ob = (const float*)d_in[i]; break; // 27
        }
    }
    float* out = (float*)d_out;

    const int smem1 = 576*28*4 + 2*128*15*8;   // 64512 + 30720 = 95232 B
    const int smem2 = (CH*OO + CH*RPIX)*4;     // 8192 + 16384 = 24576 B
    cudaFuncSetAttribute(offset_kernel, cudaFuncAttributeMaxDynamicSharedMemorySize, smem1);
    cudaFuncSetAttribute(main_kernel,  cudaFuncAttributeMaxDynamicSharedMemorySize, smem2);

    offset_kernel<<<BB*HH, 512, smem1>>>(x, wt, ow, ob);
    main_kernel<<<BB*HH*2, 256, smem2>>>(x);
    combine_kernel<<<(BB*OO*HWSZ/4)/256, 256>>>(bs, out);
}

// round 14
// speedup vs baseline: 1.0604x; 1.0604x over previous
#include <cuda_runtime.h>

#define HH 128
#define WW 128
#define CC 64
#define OO 64
#define BB 2
#define KK9 9
#define HWSZ (HH*WW)

typedef unsigned long long ull;

// ---------------- f32x2 packed helpers -----------------------------------------
__device__ __forceinline__ ull pack2(float a, float b) {
    ull r; asm("mov.b64 %0, {%1, %2};" : "=l"(r) : "f"(a), "f"(b)); return r;
}
__device__ __forceinline__ ull bcast2(float a) {
    ull r; asm("mov.b64 %0, {%1, %1};" : "=l"(r) : "f"(a)); return r;
}
__device__ __forceinline__ void ffma2(ull& d, ull a, ull b) {
    asm("fma.rn.f32x2 %0, %1, %2, %0;" : "+l"(d) : "l"(a), "l"(b));
}
__device__ __forceinline__ void fadd2(ull& d, ull a) {
    asm("add.rn.f32x2 %0, %0, %1;" : "+l"(d) : "l"(a));
}
__device__ __forceinline__ float lo2(ull v) { return __uint_as_float((unsigned)v); }
__device__ __forceinline__ float hi2(ull v) { return __uint_as_float((unsigned)(v >> 32)); }

// ---------------- scratch ------------------------------------------------------
__device__ float g_wt[KK9*CC*OO];    // main weight -> [k*64+c][o]

// ---------------- K0: main-weight reorder --------------------------------------
__global__ __launch_bounds__(256) void reorder_kernel(
    const float* __restrict__ wsrc)   // [64][64][3][3]
{
    int i = blockIdx.x * 256 + threadIdx.x;
    if (i < OO*CC*KK9) {
        int o = i / (CC*KK9);
        int r = i % (CC*KK9);
        int c = r / KK9;
        int k = r % KK9;
        g_wt[(k*CC + c)*OO + o] = wsrc[i];
    }
}

// ---------------- fused kernel --------------------------------------------------
// CTA = (b, h) full row. 512 threads. Two phases, row-local dependency only.
//
// Phase A (offset conv): threads = (pixel w 0..127) x (channel quarter 0..3),
//   each 27 conv outputs (14 f32x2) over 16 channels; quarters tree-combined
//   via smem; cq==0 runs bilinear epilogue writing metadata to SMEM.
// Phase B (sample + GEMM): 9 tap-chunks x 64 channels; sampling threads =
//   (pixel 0..127) x (channel phase 0..3, 16 ch each); GEMM tile 4o x 4p,
//   bias folded into accumulator init; writes out directly.
//
// smem (byte offsets, phase-aliased; 95232 B total):
//   A: wsh   [0, 64512)        offset weights [c][tap][28]
//      part  [64512, 95232)    combine buffer 2*128*15 ull
//   B: sIdx  [0, 18432)        int4 per (pix,k)     (over dead wsh)
//      sWgt  [18432, 36864)    float4 per (pix,k)   (over dead wsh)
//      WshB  [36864, 53248)    W chunk [64c][64o]   (over dead wsh)
//      SshB  [53248, 86016)    S chunk [64c][128p]  (over dead wsh tail + part)
__global__ __launch_bounds__(512, 2) void fused_kernel(
    const float* __restrict__ x,
    const float* __restrict__ offw,   // [27][64][3][3]
    const float* __restrict__ offb,   // [27]
    const float* __restrict__ bias,   // [64]
    float* __restrict__ out)
{
    extern __shared__ float sm[];
    float*  wsh   = sm;                       // phase A
    ull*    part  = (ull*)(sm + 16128);       // phase A combine
    int4*   sIdx  = (int4*)sm;                // phase B meta
    float4* sWgt  = (float4*)(sm + 4608);     // phase B meta
    float*  WshB  = sm + 9216;                // phase B W tile
    float*  SshB  = sm + 13312;               // phase B S tile

    int b = blockIdx.x >> 7;
    int h = blockIdx.x & 127;
    int t = threadIdx.x;

    // ================= Phase A: offset conv =================
    {
        int w  = t & 127;
        int cq = t >> 7;      // channel quarter 0..3

        // offw[j][ct] -> wsh[ct*28 + j]
        for (int i = t; i < 27*CC*KK9; i += 512) {
            int j  = i / (CC*KK9);
            int ct = i % (CC*KK9);
            wsh[ct*28 + j] = offw[i];
        }
        __syncthreads();

        ull acc2[14];
        if (cq == 0) {
            #pragma unroll
            for (int i = 0; i < 13; i++) acc2[i] = pack2(offb[2*i], offb[2*i+1]);
            acc2[13] = pack2(offb[26], 0.f);
        } else {
            #pragma unroll
            for (int i = 0; i < 14; i++) acc2[i] = 0ull;
        }

        const float* xb = x + b*CC*HWSZ;
        int c0 = cq * 16;
        for (int ci = 0; ci < 16; ci++) {
            int c = c0 + ci;
            float xv[9];
            const float* xp = xb + c*HWSZ;
            #pragma unroll
            for (int ki = 0; ki < 3; ki++) {
                int y = h - 1 + ki;
                bool yok = ((unsigned)y < HH);
                #pragma unroll
                for (int kj = 0; kj < 3; kj++) {
                    int xx = w - 1 + kj;
                    bool ok = yok && ((unsigned)xx < WW);
                    xv[ki*3+kj] = ok ? __ldg(xp + y*WW + xx) : 0.f;
                }
            }
            const float* wc = wsh + c*KK9*28;
            #pragma unroll
            for (int tap = 0; tap < 9; tap++) {
                ull xb2 = bcast2(xv[tap]);
                const ulonglong2* wt2 = (const ulonglong2*)(wc + tap*28);
                #pragma unroll
                for (int j2 = 0; j2 < 7; j2++) {
                    ulonglong2 ww = wt2[j2];
                    ffma2(acc2[j2*2    ], xb2, ww.x);
                    ffma2(acc2[j2*2 + 1], xb2, ww.y);
                }
            }
        }

        // tree combine: (2,3) -> (0,1), then 1 -> 0
        if (cq >= 2) {
            ull* dst = part + (long)(cq - 2)*128*15 + w*15;
            #pragma unroll
            for (int i = 0; i < 14; i++) dst[i] = acc2[i];
        }
        __syncthreads();   // also: all wsh reads complete after this point
        if (cq < 2) {
            ull* src = part + (long)cq*128*15 + w*15;
            #pragma unroll
            for (int i = 0; i < 14; i++) fadd2(acc2[i], src[i]);
        }
        __syncthreads();
        if (cq == 1) {
            ull* dst = part + w*15;
            #pragma unroll
            for (int i = 0; i < 14; i++) dst[i] = acc2[i];
        }
        __syncthreads();

        if (cq == 0) {
            ull* src = part + w*15;
            #pragma unroll
            for (int i = 0; i < 14; i++) fadd2(acc2[i], src[i]);

            float acc[27];
            #pragma unroll
            for (int j = 0; j < 27; j++)
                acc[j] = (j & 1) ? hi2(acc2[j >> 1]) : lo2(acc2[j >> 1]);

            // bilinear epilogue -> SMEM metadata (aliases dead wsh region)
            #pragma unroll
            for (int k = 0; k < 9; k++) {
                int ki = k / 3, kj = k % 3;
                float py = (float)(h - 1 + ki) + acc[k];
                float px = (float)(w - 1 + kj) + acc[9+k];
                float m  = 1.f / (1.f + __expf(-acc[18+k]));
                float y0f = floorf(py), x0f = floorf(px);
                float wy = py - y0f, wx = px - x0f;
                int y0 = (int)y0f, x0 = (int)x0f;
                int y1 = y0 + 1,  x1 = x0 + 1;
                bool v0y = ((unsigned)y0 < HH), v1y = ((unsigned)y1 < HH);
                bool v0x = ((unsigned)x0 < WW), v1x = ((unsigned)x1 < WW);
                float w00 = (v0y && v0x) ? (1.f-wy)*(1.f-wx)*m : 0.f;
                float w01 = (v0y && v1x) ? (1.f-wy)*wx*m       : 0.f;
                float w10 = (v1y && v0x) ? wy*(1.f-wx)*m       : 0.f;
                float w11 = (v1y && v1x) ? wy*wx*m             : 0.f;
                int cy0 = min(max(y0,0),HH-1), cy1 = min(max(y1,0),HH-1);
                int cx0 = min(max(x0,0),WW-1), cx1 = min(max(x1,0),WW-1);
                sIdx[w*KK9 + k] = make_int4(cy0*WW+cx0, cy0*WW+cx1,
                                            cy1*WW+cx0, cy1*WW+cx1);
                sWgt[w*KK9 + k] = make_float4(w00, w01, w10, w11);
            }
        }
    }
    __syncthreads();   // metadata ready for all threads

    // ================= Phase B: sample + GEMM =================
    {
        int tx  = t & 15;    // GEMM: o-quad
        int ty  = t >> 4;    // GEMM: p-quad 0..31
        int p   = t & 127;   // sampling: pixel
        int cph = t >> 7;    // sampling: channel phase 0..3 (16 ch each)

        // bias folded into accumulator init (acc packed over pixel pairs)
        ull acc2[4][2];
        #pragma unroll
        for (int i = 0; i < 4; i++) {
            ull bv = bcast2(__ldg(&bias[tx*4 + i]));
            acc2[i][0] = bv; acc2[i][1] = bv;
        }

        const float* xb = x + b*CC*HWSZ;

        for (int k = 0; k < KK9; k++) {
            // per-chunk metadata from smem (stable all phase)
            int4   id = sIdx[p*KK9 + k];
            float4 wv = sWgt[p*KK9 + k];

            __syncthreads();   // previous GEMM reads done

            // stage W chunk: g_wt rows k*64..k*64+63, contiguous 16 KB
            {
                const float4* gw = (const float4*)(g_wt + k*CC*OO);
                float4* w4 = (float4*)WshB;
                w4[t]       = gw[t];
                w4[t + 512] = gw[t + 512];
            }

            // sampling: 16 channels per thread at the fixed sample point
            #pragma unroll 8
            for (int j = 0; j < 16; j++) {
                int c = cph + j*4;
                const float* xp = xb + c*HWSZ;
                float s = wv.x*__ldg(xp+id.x) + wv.y*__ldg(xp+id.y)
                        + wv.z*__ldg(xp+id.z) + wv.w*__ldg(xp+id.w);
                SshB[c*WW + p] = s;
            }
            __syncthreads();

            // GEMM: acc[4o x 4p] += W[64 x 64] * S[64 x 128]
            #pragma unroll 4
            for (int c = 0; c < CC; c++) {
                float4     wr = *(const float4*)&WshB[c*OO + tx*4];
                ulonglong2 sv = *(const ulonglong2*)&SshB[c*WW + ty*4];
                ull b0 = bcast2(wr.x);
                ull b1 = bcast2(wr.y);
                ull b2 = bcast2(wr.z);
                ull b3 = bcast2(wr.w);
                ffma2(acc2[0][0], b0, sv.x); ffma2(acc2[0][1], b0, sv.y);
                ffma2(acc2[1][0], b1, sv.x); ffma2(acc2[1][1], b1, sv.y);
                ffma2(acc2[2][0], b2, sv.x); ffma2(acc2[2][1], b2, sv.y);
                ffma2(acc2[3][0], b3, sv.x); ffma2(acc2[3][1], b3, sv.y);
            }
        }

        // write out directly (bias already in acc)
        #pragma unroll
        for (int i = 0; i < 4; i++) {
            int o = tx*4 + i;
            float4 r = make_float4(lo2(acc2[i][0]), hi2(acc2[i][0]),
                                   lo2(acc2[i][1]), hi2(acc2[i][1]));
            *(float4*)&out[(long)(b*OO + o)*HWSZ + h*WW + ty*4] = r;
        }
    }
}

// ---------------- launch --------------------------------------------------------
extern "C" void kernel_launch(void* const* d_in, const int* in_sizes, int n_in,
                              void* d_out, int out_size)
{
    // identify inputs by element count (robust to ordering)
    const float *x = 0, *wt = 0, *bs = 0, *ow = 0, *ob = 0;
    for (int i = 0; i < n_in; i++) {
        switch (in_sizes[i]) {
            case BB*CC*HWSZ:   x  = (const float*)d_in[i]; break; // 2097152
            case OO*CC*KK9:    wt = (const float*)d_in[i]; break; // 36864
            case OO:           bs = (const float*)d_in[i]; break; // 64
            case 27*CC*KK9:    ow = (const float*)d_in[i]; break; // 15552
            case 27:           ob = (const float*)d_in[i]; break; // 27
        }
    }
    float* out = (float*)d_out;

    const int smemF = 95232;   // max(phase A 95232, phase B 86016)
    cudaFuncSetAttribute(fused_kernel, cudaFuncAttributeMaxDynamicSharedMemorySize, smemF);

    reorder_kernel<<<(OO*CC*KK9 + 255)/256, 256>>>(wt);
    fused_kernel<<<BB*HH, 512, smemF>>>(x, ow, ob, bs, out);
}